// round 1
// baseline (speedup 1.0000x reference)
#include <cuda_runtime.h>
#include <math.h>

#define NN 100000
#define EE 1250000
#define H  64

// ---------------- scratch (static __device__ — no allocation allowed) ----------------
__device__ __align__(16) float g_bufA[NN * H];
__device__ __align__(16) float g_bufB[NN * H];
__device__ __align__(16) float g_acc [NN * H];
__device__ float g_deg  [NN];
__device__ float g_dinv [NN];
__device__ float g_as   [NN];
__device__ float g_ad   [NN];
__device__ int   g_emax [NN];
__device__ float g_denom[NN];
__device__ float g_pe   [EE];
__device__ __align__(16) float g_embed[H];

// ---------------- helpers ----------------
__device__ __forceinline__ int enc_f(float f) {
    int i = __float_as_int(f);
    return i >= 0 ? i : (i ^ 0x7FFFFFFF);
}
__device__ __forceinline__ float dec_f(int i) {
    return __int_as_float(i >= 0 ? i : (i ^ 0x7FFFFFFF));
}
__device__ __forceinline__ float leaky(float v) { return v > 0.f ? v : 0.2f * v; }

// ---------------- init: acc=0, deg=1 (self-loop), embed=0 ----------------
__global__ void k_init(int n) {
    int t = blockIdx.x * blockDim.x + threadIdx.x;
    if (t < n * 16) ((float4*)g_acc)[t] = make_float4(0.f, 0.f, 0.f, 0.f);
    if (t < n) g_deg[t] = 1.0f;
    if (t < 16) ((float4*)g_embed)[t] = make_float4(0.f, 0.f, 0.f, 0.f);
}

__global__ void k_deg_edge(const int* __restrict__ dst, int e) {
    int t = blockIdx.x * blockDim.x + threadIdx.x;
    if (t < e) atomicAdd(&g_deg[dst[t]], 1.0f);
}

__global__ void k_dinv(int n) {
    int t = blockIdx.x * blockDim.x + threadIdx.x;
    if (t < n) g_dinv[t] = rsqrtf(fmaxf(g_deg[t], 1e-12f));
}

// ---------------- GEMM: [n,K] @ [K,64] ; 64 nodes/block, 64 threads ----------------
// MODE 0: out = (in @ W) * dinv  (GCN pre-scaled messages)
// MODE 1: out = in @ W ; also alpha_src/alpha_dst dots + emax init (GAT)
template <int K, int MODE>
__global__ void __launch_bounds__(64) k_gemm(
    const float* __restrict__ in, const float* __restrict__ W,
    float* __restrict__ out,
    const float* __restrict__ avs, const float* __restrict__ avd, int n)
{
    constexpr int PAD = K + 4;
    __shared__ float Ws[K * H];
    __shared__ float xs[64 * PAD];
    __shared__ float as_s[H], ad_s[H];
    const int tid  = threadIdx.x;
    const int base = blockIdx.x * 64;

    for (int i = tid; i < K * H; i += 64) Ws[i] = W[i];
    if (MODE == 1) { as_s[tid] = avs[tid]; ad_s[tid] = avd[tid]; }

    int rows = n - base; if (rows > 64) rows = 64;
    for (int i = tid; i < rows * K; i += 64) {
        int r = i / K, c = i - r * K;
        xs[r * PAD + c] = in[(size_t)(base + r) * K + c];
    }
    __syncthreads();
    if (tid >= rows) return;

    float acc[H];
#pragma unroll
    for (int j = 0; j < H; j++) acc[j] = 0.f;

#pragma unroll 4
    for (int k = 0; k < K; k++) {
        float xv = xs[tid * PAD + k];
        const float4* w4 = (const float4*)&Ws[k * H];
#pragma unroll
        for (int j4 = 0; j4 < 16; j4++) {
            float4 w = w4[j4];
            acc[4*j4+0] = fmaf(xv, w.x, acc[4*j4+0]);
            acc[4*j4+1] = fmaf(xv, w.y, acc[4*j4+1]);
            acc[4*j4+2] = fmaf(xv, w.z, acc[4*j4+2]);
            acc[4*j4+3] = fmaf(xv, w.w, acc[4*j4+3]);
        }
    }

    const int node = base + tid;
    float4* o4 = (float4*)&out[(size_t)node * H];
    if (MODE == 0) {
        float d = g_dinv[node];
#pragma unroll
        for (int j4 = 0; j4 < 16; j4++)
            o4[j4] = make_float4(acc[4*j4]*d, acc[4*j4+1]*d, acc[4*j4+2]*d, acc[4*j4+3]*d);
    } else {
        float as = 0.f, ad = 0.f;
#pragma unroll
        for (int j = 0; j < H; j++) {
            as = fmaf(acc[j], as_s[j], as);
            ad = fmaf(acc[j], ad_s[j], ad);
        }
        g_as[node] = as; g_ad[node] = ad;
        g_emax[node] = enc_f(leaky(as + ad));   // softmax max seeded with self-loop
#pragma unroll
        for (int j4 = 0; j4 < 16; j4++)
            o4[j4] = make_float4(acc[4*j4], acc[4*j4+1], acc[4*j4+2], acc[4*j4+3]);
    }
}

// ---------------- GCN edge scatter: acc[dst] += feat[src] (16 thr/edge, float4 RED) ----------------
__global__ void k_scatter(const float* __restrict__ feat,
                          const int* __restrict__ src, const int* __restrict__ dst, int e)
{
    int t = blockIdx.x * blockDim.x + threadIdx.x;
    int ei = t >> 4;
    if (ei >= e) return;
    int c = t & 15;
    int s = __ldg(&src[ei]);
    int d = __ldg(&dst[ei]);
    float4 v = __ldg((const float4*)&feat[(size_t)s * H] + c);
    atomicAdd(((float4*)&g_acc[(size_t)d * H]) + c, v);
}

// ---------------- GCN epilogue: out = relu((acc + hs)*dinv + b), re-zero acc ----------------
__global__ void k_gcn_epi(const float* __restrict__ hs, const float* __restrict__ b,
                          float* __restrict__ out, int n)
{
    int t = blockIdx.x * blockDim.x + threadIdx.x;
    if (t >= n * 16) return;
    int node = t >> 4, j4 = t & 15;
    float d   = g_dinv[node];
    float4 a  = ((float4*)g_acc)[t];
    float4 h  = __ldg((const float4*)hs + t);
    float4 bb = __ldg((const float4*)b + j4);
    float4 r;
    r.x = fmaxf(fmaf(a.x + h.x, d, bb.x), 0.f);
    r.y = fmaxf(fmaf(a.y + h.y, d, bb.y), 0.f);
    r.z = fmaxf(fmaf(a.z + h.z, d, bb.z), 0.f);
    r.w = fmaxf(fmaf(a.w + h.w, d, bb.w), 0.f);
    ((float4*)out)[t] = r;
    ((float4*)g_acc)[t] = make_float4(0.f, 0.f, 0.f, 0.f);
}

// ---------------- GAT passes ----------------
__global__ void k_gat_emax(const int* __restrict__ src, const int* __restrict__ dst, int e) {
    int t = blockIdx.x * blockDim.x + threadIdx.x;
    if (t >= e) return;
    int d = dst[t];
    float ev = leaky(g_as[src[t]] + g_ad[d]);
    atomicMax(&g_emax[d], enc_f(ev));
}

__global__ void k_gat_mid(int n) {   // denom seeded with self-loop term
    int t = blockIdx.x * blockDim.x + threadIdx.x;
    if (t >= n) return;
    float m = dec_f(g_emax[t]);
    g_denom[t] = expf(leaky(g_as[t] + g_ad[t]) - m);
}

__global__ void k_gat_p(const int* __restrict__ src, const int* __restrict__ dst, int e) {
    int t = blockIdx.x * blockDim.x + threadIdx.x;
    if (t >= e) return;
    int d = dst[t];
    float ev = leaky(g_as[src[t]] + g_ad[d]);
    float p = expf(ev - dec_f(g_emax[d]));
    g_pe[t] = p;
    atomicAdd(&g_denom[d], p);
}

__global__ void k_gat_scatter(const int* __restrict__ src, const int* __restrict__ dst, int e) {
    int t = blockIdx.x * blockDim.x + threadIdx.x;
    int ei = t >> 4;
    if (ei >= e) return;
    int c = t & 15;
    int s = __ldg(&src[ei]);
    int d = __ldg(&dst[ei]);
    float w = g_pe[ei] / g_denom[d];
    float4 v = __ldg((const float4*)&g_bufA[(size_t)s * H] + c);
    v.x *= w; v.y *= w; v.z *= w; v.w *= w;
    atomicAdd(((float4*)&g_acc[(size_t)d * H]) + c, v);
}

__global__ void k_gat_epi(const float* __restrict__ b2, float* __restrict__ out, int n) {
    int t = blockIdx.x * blockDim.x + threadIdx.x;
    if (t >= n * 16) return;
    int node = t >> 4, j4 = t & 15;
    float m  = dec_f(g_emax[node]);
    float ws = expf(leaky(g_as[node] + g_ad[node]) - m) / g_denom[node];
    float4 a  = ((float4*)g_acc)[t];
    float4 h  = ((const float4*)g_bufA)[t];
    float4 bb = __ldg((const float4*)b2 + j4);
    float4 r;
    r.x = fmaxf(fmaf(h.x, ws, a.x) + bb.x, 0.f);
    r.y = fmaxf(fmaf(h.y, ws, a.y) + bb.y, 0.f);
    r.z = fmaxf(fmaf(h.z, ws, a.z) + bb.z, 0.f);
    r.w = fmaxf(fmaf(h.w, ws, a.w) + bb.w, 0.f);
    ((float4*)out)[t] = r;
    ((float4*)g_acc)[t] = make_float4(0.f, 0.f, 0.f, 0.f);
}

// ---------------- heads: opt logits, bottleneck MLP, embedding partials ----------------
__global__ void __launch_bounds__(128) k_heads(
    const float* __restrict__ h,
    const float* __restrict__ Wopt, const float* __restrict__ bopt,
    const float* __restrict__ Wb1,  const float* __restrict__ bb1,
    const float* __restrict__ Wb2,  const float* __restrict__ bb2,
    float* __restrict__ out_opt, float* __restrict__ out_bot, int n)
{
    __shared__ float sWopt[H * 10], sbopt[10], sWb1[H * 32], sbb1[32], sWb2[32], sbb2[1];
    const int tid = threadIdx.x;
    for (int i = tid; i < H * 10; i += 128) sWopt[i] = Wopt[i];
    for (int i = tid; i < H * 32; i += 128) sWb1[i] = Wb1[i];
    if (tid < 10) sbopt[tid] = bopt[tid];
    if (tid < 32) { sbb1[tid] = bb1[tid]; sWb2[tid] = Wb2[tid]; }
    if (tid == 0) sbb2[0] = bb2[0];
    __syncthreads();

    const int node = blockIdx.x * 128 + tid;
    float hv[H];
    if (node < n) {
        const float4* h4 = (const float4*)&h[(size_t)node * H];
#pragma unroll
        for (int j4 = 0; j4 < 16; j4++) {
            float4 v = h4[j4];
            hv[4*j4] = v.x; hv[4*j4+1] = v.y; hv[4*j4+2] = v.z; hv[4*j4+3] = v.w;
        }
        for (int c = 0; c < 10; c++) {
            float s = sbopt[c];
#pragma unroll
            for (int j = 0; j < H; j++) s = fmaf(hv[j], sWopt[j * 10 + c], s);
            out_opt[(size_t)node * 10 + c] = s;
        }
        float z = sbb2[0];
        for (int m = 0; m < 32; m++) {
            float s = sbb1[m];
#pragma unroll
            for (int j = 0; j < H; j++) s = fmaf(hv[j], sWb1[j * 32 + m], s);
            z = fmaf(fmaxf(s, 0.f), sWb2[m], z);
        }
        out_bot[node] = 1.f / (1.f + expf(-z));
    } else {
#pragma unroll
        for (int j = 0; j < H; j++) hv[j] = 0.f;
    }

    // embedding: warp-reduce each channel then one RED per warp/channel
#pragma unroll
    for (int j = 0; j < H; j++) {
        float v = hv[j];
        v += __shfl_xor_sync(0xffffffffu, v, 16);
        v += __shfl_xor_sync(0xffffffffu, v, 8);
        v += __shfl_xor_sync(0xffffffffu, v, 4);
        v += __shfl_xor_sync(0xffffffffu, v, 2);
        v += __shfl_xor_sync(0xffffffffu, v, 1);
        if ((tid & 31) == 0) atomicAdd(&g_embed[j], v);
    }
}

__global__ void k_embed_final(float* __restrict__ emb_out, float inv_n) {
    int t = threadIdx.x;
    if (t < H) emb_out[t] = g_embed[t] * inv_n;
}

// ---------------- launcher ----------------
extern "C" void kernel_launch(void* const* d_in, const int* in_sizes, int n_in,
                              void* d_out, int out_size)
{
    const float* x    = (const float*)d_in[0];
    const int*   ei   = (const int*)  d_in[1];
    const float* W1   = (const float*)d_in[2];
    const float* b1   = (const float*)d_in[3];
    const float* W2   = (const float*)d_in[4];
    const float* avs  = (const float*)d_in[5];
    const float* avd  = (const float*)d_in[6];
    const float* b2   = (const float*)d_in[7];
    const float* W3   = (const float*)d_in[8];
    const float* b3   = (const float*)d_in[9];
    const float* Wopt = (const float*)d_in[10];
    const float* bopt = (const float*)d_in[11];
    const float* Wb1  = (const float*)d_in[12];
    const float* bb1  = (const float*)d_in[13];
    const float* Wb2  = (const float*)d_in[14];
    const float* bb2  = (const float*)d_in[15];

    const int n = in_sizes[0] / 32;   // F = 32
    const int e = in_sizes[1] / 2;
    const int* src = ei;
    const int* dst = ei + e;

    float* out_opt = (float*)d_out;
    float* out_bot = out_opt + (size_t)n * 10;
    float* out_emb = out_bot + n;

    float *bufA = nullptr, *bufB = nullptr;
    cudaGetSymbolAddress((void**)&bufA, g_bufA);
    cudaGetSymbolAddress((void**)&bufB, g_bufB);

    const int B = 256;
    const int gN   = (n + B - 1) / B;
    const int gN16 = (n * 16 + B - 1) / B;
    const int gE   = (e + B - 1) / B;
    const int gE16 = (e * 16 + B - 1) / B;   // e*16 = 20M < INT_MAX
    const int gG   = (n + 63) / 64;

    // degree / norm (shared by both GCN layers; self-loop => deg init 1)
    k_init<<<gN16, B>>>(n);
    k_deg_edge<<<gE, B>>>(dst, e);
    k_dinv<<<gN, B>>>(n);

    // GCN layer 1
    k_gemm<32, 0><<<gG, 64>>>(x, W1, bufA, nullptr, nullptr, n);
    k_scatter<<<gE16, B>>>(bufA, src, dst, e);
    k_gcn_epi<<<gN16, B>>>(bufA, b1, bufB, n);

    // GAT layer
    k_gemm<64, 1><<<gG, 64>>>(bufB, W2, bufA, avs, avd, n);
    k_gat_emax<<<gE, B>>>(src, dst, e);
    k_gat_mid<<<gN, B>>>(n);
    k_gat_p<<<gE, B>>>(src, dst, e);
    k_gat_scatter<<<gE16, B>>>(src, dst, e);
    k_gat_epi<<<gN16, B>>>(b2, bufB, n);

    // GCN layer 3
    k_gemm<64, 0><<<gG, 64>>>(bufB, W3, bufA, nullptr, nullptr, n);
    k_scatter<<<gE16, B>>>(bufA, src, dst, e);
    k_gcn_epi<<<gN16, B>>>(bufA, b3, bufB, n);

    // heads + embedding
    k_heads<<<(n + 127) / 128, 128>>>(bufB, Wopt, bopt, Wb1, bb1, Wb2, bb2,
                                      out_opt, out_bot, n);
    k_embed_final<<<1, 64>>>(out_emb, 1.0f / (float)n);
}

// round 4
// speedup vs baseline: 1.4759x; 1.4759x over previous
#include <cuda_runtime.h>
#include <math.h>

#define NN 100000
#define EE 1250000
#define H  64

// ---------------- scratch (static __device__ — no allocation allowed) ----------------
__device__ __align__(16) float g_bufA[NN * H];
__device__ __align__(16) float g_bufB[NN * H];
__device__ float g_dinv [NN];
__device__ float g_as   [NN];
__device__ float g_ad   [NN];
__device__ int   g_degi [NN];
__device__ int   g_scan [NN];
__device__ int   g_bsum [128];
__device__ int   g_boff [128];
__device__ int   g_row  [NN + 1];
__device__ int   g_cur  [NN];
__device__ int   g_csrc [EE];
__device__ __align__(16) float g_embed[H];

__device__ __forceinline__ float leaky(float v) { return v > 0.f ? v : 0.2f * v; }

// ---------------- prep: zero degree histogram + embed ----------------
__global__ void k_prep(int n) {
    int t = blockIdx.x * blockDim.x + threadIdx.x;
    if (t < n) g_degi[t] = 0;
    if (t < 16) ((float4*)g_embed)[t] = make_float4(0.f, 0.f, 0.f, 0.f);
}

__global__ void k_deg(const int* __restrict__ dst, int e) {
    int t = blockIdx.x * blockDim.x + threadIdx.x;
    if (t < e) atomicAdd(&g_degi[dst[t]], 1);
}

// ---------------- scan (1024-wide blocks, Hillis-Steele) ----------------
__global__ void k_scan1(int n) {
    __shared__ int sh[1024];
    int i = blockIdx.x * 1024 + threadIdx.x;
    int v = (i < n) ? g_degi[i] : 0;
    sh[threadIdx.x] = v; __syncthreads();
    for (int o = 1; o < 1024; o <<= 1) {
        int u = (threadIdx.x >= o) ? sh[threadIdx.x - o] : 0;
        __syncthreads();
        sh[threadIdx.x] += u;
        __syncthreads();
    }
    if (i < n) g_scan[i] = sh[threadIdx.x];
    if (threadIdx.x == 1023) g_bsum[blockIdx.x] = sh[1023];
}

__global__ void k_scan2(int nb) {
    __shared__ int sh[128];
    int t = threadIdx.x;
    int v = (t < nb) ? g_bsum[t] : 0;
    sh[t] = v; __syncthreads();
    for (int o = 1; o < 128; o <<= 1) {
        int u = (t >= o) ? sh[t - o] : 0;
        __syncthreads();
        sh[t] += u;
        __syncthreads();
    }
    if (t < nb) g_boff[t] = sh[t] - v;  // exclusive
}

__global__ void k_scan3(int n, int e) {
    int i = blockIdx.x * blockDim.x + threadIdx.x;
    if (i < n) {
        int d = g_degi[i];
        int start = g_scan[i] - d + g_boff[i >> 10];
        g_row[i] = start;
        g_cur[i] = start;
        g_dinv[i] = rsqrtf((float)(d + 1));   // +1 self-loop
    }
    if (i == 0) g_row[n] = e;
}

__global__ void k_csr(const int* __restrict__ src, const int* __restrict__ dst, int e) {
    int t = blockIdx.x * blockDim.x + threadIdx.x;
    if (t >= e) return;
    int pos = atomicAdd(&g_cur[dst[t]], 1);
    g_csrc[pos] = src[t];
}

// ---------------- GEMM: [n,K] @ [K,64] ; 128 nodes/block, 256 threads ----------------
// 2 threads per node; thread (node, half) owns interleaved float4 channels {2j+half}.
// MODE 0: out = (in @ W) * dinv[node]   (GCN pre-scaled messages)
// MODE 1: out = in @ W ; also alpha_src/alpha_dst dots (GAT)
template <int K, int MODE>
__global__ void __launch_bounds__(256) k_gemm(
    const float* __restrict__ in, const float* __restrict__ W,
    float* __restrict__ out,
    const float* __restrict__ avs, const float* __restrict__ avd, int n)
{
    constexpr int PAD = K + 1;                 // odd -> conflict-free
    __shared__ float Ws[K * H];
    __shared__ float xs[128 * PAD];
    __shared__ float as_s[H], ad_s[H];
    const int tid  = threadIdx.x;
    const int base = blockIdx.x * 128;

    for (int i = tid; i < K * H; i += 256) Ws[i] = W[i];
    if (MODE == 1 && tid < H) { as_s[tid] = avs[tid]; ad_s[tid] = avd[tid]; }

    int rows = n - base; if (rows > 128) rows = 128;
    for (int i = tid; i < rows * K; i += 256) {
        int r = i / K, c = i - r * K;
        xs[r * PAD + c] = in[(size_t)(base + r) * K + c];
    }
    __syncthreads();

    const int r     = tid >> 1;
    const bool valid = (r < rows);
    const int rc    = valid ? r : 0;
    const int half  = tid & 1;

    float acc[32];
#pragma unroll
    for (int j = 0; j < 32; j++) acc[j] = 0.f;

    const float* xrow = &xs[rc * PAD];
#pragma unroll 4
    for (int k = 0; k < K; k++) {
        float xv = xrow[k];
        const float4* w4 = (const float4*)&Ws[k * H];
#pragma unroll
        for (int j = 0; j < 8; j++) {
            float4 w = w4[j * 2 + half];
            acc[4*j+0] = fmaf(xv, w.x, acc[4*j+0]);
            acc[4*j+1] = fmaf(xv, w.y, acc[4*j+1]);
            acc[4*j+2] = fmaf(xv, w.z, acc[4*j+2]);
            acc[4*j+3] = fmaf(xv, w.w, acc[4*j+3]);
        }
    }

    const int node = base + r;
    if (MODE == 0) {
        if (!valid) return;
        float d = g_dinv[node];
        float4* o4 = (float4*)&out[(size_t)node * H];
#pragma unroll
        for (int j = 0; j < 8; j++)
            o4[j * 2 + half] = make_float4(acc[4*j]*d, acc[4*j+1]*d, acc[4*j+2]*d, acc[4*j+3]*d);
    } else {
        float as = 0.f, ad = 0.f;
#pragma unroll
        for (int j = 0; j < 8; j++) {
#pragma unroll
            for (int q = 0; q < 4; q++) {
                int ch = (j * 2 + half) * 4 + q;
                as = fmaf(acc[4*j+q], as_s[ch], as);
                ad = fmaf(acc[4*j+q], ad_s[ch], ad);
            }
        }
        // combine the two halves of the node (no early exit before shuffles)
        as += __shfl_xor_sync(0xffffffffu, as, 1);
        ad += __shfl_xor_sync(0xffffffffu, ad, 1);
        if (valid) {
            if (half == 0) { g_as[node] = as; g_ad[node] = ad; }
            float4* o4 = (float4*)&out[(size_t)node * H];
#pragma unroll
            for (int j = 0; j < 8; j++)
                o4[j * 2 + half] = make_float4(acc[4*j], acc[4*j+1], acc[4*j+2], acc[4*j+3]);
        }
    }
}

// ---------------- GCN gather + epilogue: out = relu((Σ hs[src] + hs[d]) * dinv[d] + b) ----------------
__global__ void __launch_bounds__(256) k_gcn_gather(
    const float* __restrict__ hs, const float* __restrict__ b,
    float* __restrict__ out, int n)
{
    int t = blockIdx.x * blockDim.x + threadIdx.x;
    int node = t >> 4;
    if (node >= n) return;
    int c = t & 15;

    int beg = g_row[node], end = g_row[node + 1];
    float4 acc = __ldg((const float4*)&hs[(size_t)node * H] + c);   // self-loop
    for (int i = beg; i < end; i++) {
        int s = __ldg(&g_csrc[i]);
        float4 v = __ldg((const float4*)&hs[(size_t)s * H] + c);
        acc.x += v.x; acc.y += v.y; acc.z += v.z; acc.w += v.w;
    }
    float dv = g_dinv[node];
    float4 bb = __ldg((const float4*)b + c);
    float4 r;
    r.x = fmaxf(fmaf(acc.x, dv, bb.x), 0.f);
    r.y = fmaxf(fmaf(acc.y, dv, bb.y), 0.f);
    r.z = fmaxf(fmaf(acc.z, dv, bb.z), 0.f);
    r.w = fmaxf(fmaf(acc.w, dv, bb.w), 0.f);
    ((float4*)&out[(size_t)node * H])[c] = r;
}

// ---------------- GAT gather: softmax-max, then fused p/denom/weighted gather + epilogue ----------------
__global__ void __launch_bounds__(256) k_gat_gather(
    const float* __restrict__ h2, const float* __restrict__ b2,
    float* __restrict__ out, int n)
{
    int t = blockIdx.x * blockDim.x + threadIdx.x;
    int node = t >> 4;
    int c = t & 15;
    bool valid = (node < n);
    int nd = valid ? node : 0;

    int beg = g_row[nd], end = g_row[nd + 1];
    if (!valid) { beg = 0; end = 0; }

    float ad_d   = g_ad[nd];
    float eself  = leaky(g_as[nd] + ad_d);

    // pass 1: max over incoming edges (edge-parallel across the 16 lanes)
    float m = eself;
    for (int i = beg + c; i < end; i += 16) {
        int s = __ldg(&g_csrc[i]);
        m = fmaxf(m, leaky(__ldg(&g_as[s]) + ad_d));
    }
#pragma unroll
    for (int o = 8; o; o >>= 1)
        m = fmaxf(m, __shfl_xor_sync(0xffffffffu, m, o));   // stays in 16-lane group

    // pass 2: accumulate p*h2[src] and denom (channel-parallel)
    float4 acc = make_float4(0.f, 0.f, 0.f, 0.f);
    float den = 0.f;
    for (int i = beg; i < end; i++) {
        int s = __ldg(&g_csrc[i]);
        float p = __expf(leaky(__ldg(&g_as[s]) + ad_d) - m);
        float4 v = __ldg((const float4*)&h2[(size_t)s * H] + c);
        acc.x = fmaf(p, v.x, acc.x); acc.y = fmaf(p, v.y, acc.y);
        acc.z = fmaf(p, v.z, acc.z); acc.w = fmaf(p, v.w, acc.w);
        den += p;
    }
    if (!valid) return;

    float pself = __expf(eself - m);
    float w = 1.f / (den + pself);
    float4 hd = __ldg((const float4*)&h2[(size_t)node * H] + c);
    float4 bb = __ldg((const float4*)b2 + c);
    float4 r;
    r.x = fmaxf(fmaf(acc.x + pself * hd.x, w, bb.x), 0.f);
    r.y = fmaxf(fmaf(acc.y + pself * hd.y, w, bb.y), 0.f);
    r.z = fmaxf(fmaf(acc.z + pself * hd.z, w, bb.z), 0.f);
    r.w = fmaxf(fmaf(acc.w + pself * hd.w, w, bb.w), 0.f);
    ((float4*)&out[(size_t)node * H])[c] = r;
}

// ---------------- heads: opt logits, bottleneck MLP, embedding partials ----------------
__global__ void __launch_bounds__(128) k_heads(
    const float* __restrict__ h,
    const float* __restrict__ Wopt, const float* __restrict__ bopt,
    const float* __restrict__ Wb1,  const float* __restrict__ bb1,
    const float* __restrict__ Wb2,  const float* __restrict__ bb2,
    float* __restrict__ out_opt, float* __restrict__ out_bot, int n)
{
    __shared__ float sWopt[H * 10], sbopt[10], sWb1[H * 32], sbb1[32], sWb2[32], sbb2[1];
    const int tid = threadIdx.x;
    for (int i = tid; i < H * 10; i += 128) sWopt[i] = Wopt[i];
    for (int i = tid; i < H * 32; i += 128) sWb1[i] = Wb1[i];
    if (tid < 10) sbopt[tid] = bopt[tid];
    if (tid < 32) { sbb1[tid] = bb1[tid]; sWb2[tid] = Wb2[tid]; }
    if (tid == 0) sbb2[0] = bb2[0];
    __syncthreads();

    const int node = blockIdx.x * 128 + tid;
    float hv[H];
    if (node < n) {
        const float4* h4 = (const float4*)&h[(size_t)node * H];
#pragma unroll
        for (int j4 = 0; j4 < 16; j4++) {
            float4 v = h4[j4];
            hv[4*j4] = v.x; hv[4*j4+1] = v.y; hv[4*j4+2] = v.z; hv[4*j4+3] = v.w;
        }
        for (int c = 0; c < 10; c++) {
            float s = sbopt[c];
#pragma unroll
            for (int j = 0; j < H; j++) s = fmaf(hv[j], sWopt[j * 10 + c], s);
            out_opt[(size_t)node * 10 + c] = s;
        }
        float z = sbb2[0];
        for (int m = 0; m < 32; m++) {
            float s = sbb1[m];
#pragma unroll
            for (int j = 0; j < H; j++) s = fmaf(hv[j], sWb1[j * 32 + m], s);
            z = fmaf(fmaxf(s, 0.f), sWb2[m], z);
        }
        out_bot[node] = 1.f / (1.f + expf(-z));
    } else {
#pragma unroll
        for (int j = 0; j < H; j++) hv[j] = 0.f;
    }

#pragma unroll
    for (int j = 0; j < H; j++) {
        float v = hv[j];
        v += __shfl_xor_sync(0xffffffffu, v, 16);
        v += __shfl_xor_sync(0xffffffffu, v, 8);
        v += __shfl_xor_sync(0xffffffffu, v, 4);
        v += __shfl_xor_sync(0xffffffffu, v, 2);
        v += __shfl_xor_sync(0xffffffffu, v, 1);
        if ((tid & 31) == 0) atomicAdd(&g_embed[j], v);
    }
}

__global__ void k_embed_final(float* __restrict__ emb_out, float inv_n) {
    int t = threadIdx.x;
    if (t < H) emb_out[t] = g_embed[t] * inv_n;
}

// ---------------- launcher ----------------
extern "C" void kernel_launch(void* const* d_in, const int* in_sizes, int n_in,
                              void* d_out, int out_size)
{
    const float* x    = (const float*)d_in[0];
    const int*   ei   = (const int*)  d_in[1];
    const float* W1   = (const float*)d_in[2];
    const float* b1   = (const float*)d_in[3];
    const float* W2   = (const float*)d_in[4];
    const float* avs  = (const float*)d_in[5];
    const float* avd  = (const float*)d_in[6];
    const float* b2   = (const float*)d_in[7];
    const float* W3   = (const float*)d_in[8];
    const float* b3   = (const float*)d_in[9];
    const float* Wopt = (const float*)d_in[10];
    const float* bopt = (const float*)d_in[11];
    const float* Wb1  = (const float*)d_in[12];
    const float* bb1  = (const float*)d_in[13];
    const float* Wb2  = (const float*)d_in[14];
    const float* bb2  = (const float*)d_in[15];

    const int n = in_sizes[0] / 32;   // F = 32
    const int e = in_sizes[1] / 2;
    const int* src = ei;
    const int* dst = ei + e;

    float* out_opt = (float*)d_out;
    float* out_bot = out_opt + (size_t)n * 10;
    float* out_emb = out_bot + n;

    float *bufA = nullptr, *bufB = nullptr;
    cudaGetSymbolAddress((void**)&bufA, g_bufA);
    cudaGetSymbolAddress((void**)&bufB, g_bufB);

    const int B = 256;
    const int gN   = (n + B - 1) / B;
    const int gE   = (e + B - 1) / B;
    const int gN16 = (n * 16 + B - 1) / B;
    const int gG   = (n + 127) / 128;
    const int nb   = (n + 1023) / 1024;

    // CSR build (degree histogram -> scan -> cursor scatter)
    k_prep<<<gN, B>>>(n);
    k_deg<<<gE, B>>>(dst, e);
    k_scan1<<<nb, 1024>>>(n);
    k_scan2<<<1, 128>>>(nb);
    k_scan3<<<gN, B>>>(n, e);
    k_csr<<<gE, B>>>(src, dst, e);

    // GCN layer 1
    k_gemm<32, 0><<<gG, 256>>>(x, W1, bufA, nullptr, nullptr, n);
    k_gcn_gather<<<gN16, B>>>(bufA, b1, bufB, n);

    // GAT layer
    k_gemm<64, 1><<<gG, 256>>>(bufB, W2, bufA, avs, avd, n);
    k_gat_gather<<<gN16, B>>>(bufA, b2, bufB, n);

    // GCN layer 3
    k_gemm<64, 0><<<gG, 256>>>(bufB, W3, bufA, nullptr, nullptr, n);
    k_gcn_gather<<<gN16, B>>>(bufA, b3, bufB, n);

    // heads + embedding
    k_heads<<<(n + 127) / 128, 128>>>(bufB, Wopt, bopt, Wb1, bb1, Wb2, bb2,
                                      out_opt, out_bot, n);
    k_embed_final<<<1, 64>>>(out_emb, 1.0f / (float)n);
}

// round 6
// speedup vs baseline: 2.3204x; 1.5722x over previous
#include <cuda_runtime.h>
#include <math.h>

#define NN 100000
#define EE 1250000
#define H  64

// ---------------- scratch (static __device__ — no allocation allowed) ----------------
__device__ __align__(16) float g_bufA[NN * H];
__device__ __align__(16) float g_bufB[NN * H];
__device__ __align__(16) float g_t32 [NN * 32];
__device__ float g_dinv [NN];
__device__ float g_as   [NN];
__device__ float g_ad   [NN];
__device__ int   g_degi [NN];
__device__ int   g_scan [NN];
__device__ int   g_bsum [128];
__device__ int   g_boff [128];
__device__ int   g_row  [NN + 1];
__device__ int   g_cur  [NN];
__device__ int   g_csrc [EE];
__device__ __align__(16) float g_embed[H];

__device__ __forceinline__ float leaky(float v) { return v > 0.f ? v : 0.2f * v; }

// ---------------- prep: zero degree histogram + embed ----------------
__global__ void k_prep(int n) {
    int t = blockIdx.x * blockDim.x + threadIdx.x;
    if (t < n) g_degi[t] = 0;
    if (t < 16) ((float4*)g_embed)[t] = make_float4(0.f, 0.f, 0.f, 0.f);
}

__global__ void k_deg(const int* __restrict__ dst, int e) {
    int t = blockIdx.x * blockDim.x + threadIdx.x;
    if (t < e) atomicAdd(&g_degi[dst[t]], 1);
}

// ---------------- scan (1024-wide blocks, Hillis-Steele) ----------------
__global__ void k_scan1(int n) {
    __shared__ int sh[1024];
    int i = blockIdx.x * 1024 + threadIdx.x;
    int v = (i < n) ? g_degi[i] : 0;
    sh[threadIdx.x] = v; __syncthreads();
    for (int o = 1; o < 1024; o <<= 1) {
        int u = (threadIdx.x >= o) ? sh[threadIdx.x - o] : 0;
        __syncthreads();
        sh[threadIdx.x] += u;
        __syncthreads();
    }
    if (i < n) g_scan[i] = sh[threadIdx.x];
    if (threadIdx.x == 1023) g_bsum[blockIdx.x] = sh[1023];
}

__global__ void k_scan2(int nb) {
    __shared__ int sh[128];
    int t = threadIdx.x;
    int v = (t < nb) ? g_bsum[t] : 0;
    sh[t] = v; __syncthreads();
    for (int o = 1; o < 128; o <<= 1) {
        int u = (t >= o) ? sh[t - o] : 0;
        __syncthreads();
        sh[t] += u;
        __syncthreads();
    }
    if (t < nb) g_boff[t] = sh[t] - v;  // exclusive
}

__global__ void k_scan3(int n, int e) {
    int i = blockIdx.x * blockDim.x + threadIdx.x;
    if (i < n) {
        int d = g_degi[i];
        int start = g_scan[i] - d + g_boff[i >> 10];
        g_row[i] = start;
        g_cur[i] = start;
        g_dinv[i] = rsqrtf((float)(d + 1));   // +1 self-loop
    }
    if (i == 0) g_row[n] = e;
}

__global__ void k_csr(const int* __restrict__ src, const int* __restrict__ dst, int e) {
    int t = blockIdx.x * blockDim.x + threadIdx.x;
    if (t >= e) return;
    int pos = atomicAdd(&g_cur[dst[t]], 1);
    g_csrc[pos] = src[t];
}

// ---------------- gather in F=32 space: t = dinv_d*x[d] + Σ dinv_s*x[s]  (8 lanes/node) ----
__global__ void __launch_bounds__(256) k_gather32(const float* __restrict__ x,
                                                  float* __restrict__ t, int n)
{
    int tt = blockIdx.x * blockDim.x + threadIdx.x;
    int node = tt >> 3;
    if (node >= n) return;
    int c = tt & 7;

    int beg = g_row[node], end = g_row[node + 1];
    float dd = g_dinv[node];
    float4 self = __ldg((const float4*)x + (size_t)node * 8 + c);
    float4 acc = make_float4(self.x * dd, self.y * dd, self.z * dd, self.w * dd);

    int i = beg;
    for (; i + 2 <= end; i += 2) {
        int s0 = __ldg(&g_csrc[i]);
        int s1 = __ldg(&g_csrc[i + 1]);
        float d0 = __ldg(&g_dinv[s0]);
        float d1 = __ldg(&g_dinv[s1]);
        float4 v0 = __ldg((const float4*)x + (size_t)s0 * 8 + c);
        float4 v1 = __ldg((const float4*)x + (size_t)s1 * 8 + c);
        acc.x += d0 * v0.x + d1 * v1.x;
        acc.y += d0 * v0.y + d1 * v1.y;
        acc.z += d0 * v0.z + d1 * v1.z;
        acc.w += d0 * v0.w + d1 * v1.w;
    }
    if (i < end) {
        int s0 = __ldg(&g_csrc[i]);
        float d0 = __ldg(&g_dinv[s0]);
        float4 v0 = __ldg((const float4*)x + (size_t)s0 * 8 + c);
        acc.x += d0 * v0.x; acc.y += d0 * v0.y;
        acc.z += d0 * v0.z; acc.w += d0 * v0.w;
    }
    ((float4*)t)[(size_t)node * 8 + c] = acc;
}

// ---------------- gather in H=64 space: u = dinv_d*h[d] + Σ dinv_s*h[s]  (16 lanes/node) ----
__global__ void __launch_bounds__(256) k_gather64(const float* __restrict__ h,
                                                  float* __restrict__ u, int n)
{
    int tt = blockIdx.x * blockDim.x + threadIdx.x;
    int node = tt >> 4;
    if (node >= n) return;
    int c = tt & 15;

    int beg = g_row[node], end = g_row[node + 1];
    float dd = g_dinv[node];
    float4 self = __ldg((const float4*)h + (size_t)node * 16 + c);
    float4 acc = make_float4(self.x * dd, self.y * dd, self.z * dd, self.w * dd);

    int i = beg;
    for (; i + 2 <= end; i += 2) {
        int s0 = __ldg(&g_csrc[i]);
        int s1 = __ldg(&g_csrc[i + 1]);
        float d0 = __ldg(&g_dinv[s0]);
        float d1 = __ldg(&g_dinv[s1]);
        float4 v0 = __ldg((const float4*)h + (size_t)s0 * 16 + c);
        float4 v1 = __ldg((const float4*)h + (size_t)s1 * 16 + c);
        acc.x += d0 * v0.x + d1 * v1.x;
        acc.y += d0 * v0.y + d1 * v1.y;
        acc.z += d0 * v0.z + d1 * v1.z;
        acc.w += d0 * v0.w + d1 * v1.w;
    }
    if (i < end) {
        int s0 = __ldg(&g_csrc[i]);
        float d0 = __ldg(&g_dinv[s0]);
        float4 v0 = __ldg((const float4*)h + (size_t)s0 * 16 + c);
        acc.x += d0 * v0.x; acc.y += d0 * v0.y;
        acc.z += d0 * v0.z; acc.w += d0 * v0.w;
    }
    ((float4*)u)[(size_t)node * 16 + c] = acc;
}

// ---------------- GEMM: [n,K] @ [K,64] ; 128 nodes/block, 256 threads ----------------
// 2 threads/node; thread (node, half) owns interleaved float4 channels {2j+half}.
// MODE 0: out = relu(dinv[node]*(in @ W) + bias)   (GCN, aggregate-first)
// MODE 1: out = in @ W ; also alpha_src/alpha_dst dots (GAT)
template <int K, int MODE>
__global__ void __launch_bounds__(256) k_gemm(
    const float* __restrict__ in, const float* __restrict__ W,
    float* __restrict__ out, const float* __restrict__ bias,
    const float* __restrict__ avs, const float* __restrict__ avd, int n)
{
    constexpr int PAD = K + 1;                 // odd -> conflict-free
    __shared__ float Ws[K * H];
    __shared__ float xs[128 * PAD];
    __shared__ float as_s[H], ad_s[H], bs[H];
    const int tid  = threadIdx.x;
    const int base = blockIdx.x * 128;

    for (int i = tid; i < K * H; i += 256) Ws[i] = W[i];
    if (MODE == 1 && tid < H) { as_s[tid] = avs[tid]; ad_s[tid] = avd[tid]; }
    if (MODE == 0 && tid < H) bs[tid] = bias[tid];

    int rows = n - base; if (rows > 128) rows = 128;
    for (int i = tid; i < rows * K; i += 256) {
        int r = i / K, c = i - r * K;
        xs[r * PAD + c] = in[(size_t)(base + r) * K + c];
    }
    __syncthreads();

    const int r     = tid >> 1;
    const bool valid = (r < rows);
    const int rc    = valid ? r : 0;
    const int half  = tid & 1;

    float acc[32];
#pragma unroll
    for (int j = 0; j < 32; j++) acc[j] = 0.f;

    const float* xrow = &xs[rc * PAD];
#pragma unroll 4
    for (int k = 0; k < K; k++) {
        float xv = xrow[k];
        const float4* w4 = (const float4*)&Ws[k * H];
#pragma unroll
        for (int j = 0; j < 8; j++) {
            float4 w = w4[j * 2 + half];
            acc[4*j+0] = fmaf(xv, w.x, acc[4*j+0]);
            acc[4*j+1] = fmaf(xv, w.y, acc[4*j+1]);
            acc[4*j+2] = fmaf(xv, w.z, acc[4*j+2]);
            acc[4*j+3] = fmaf(xv, w.w, acc[4*j+3]);
        }
    }

    const int node = base + r;
    if (MODE == 0) {
        if (!valid) return;
        float d = g_dinv[node];
        float4* o4 = (float4*)&out[(size_t)node * H];
#pragma unroll
        for (int j = 0; j < 8; j++) {
            int ch = (j * 2 + half) * 4;
            o4[j * 2 + half] = make_float4(
                fmaxf(fmaf(acc[4*j+0], d, bs[ch+0]), 0.f),
                fmaxf(fmaf(acc[4*j+1], d, bs[ch+1]), 0.f),
                fmaxf(fmaf(acc[4*j+2], d, bs[ch+2]), 0.f),
                fmaxf(fmaf(acc[4*j+3], d, bs[ch+3]), 0.f));
        }
    } else {
        float as = 0.f, ad = 0.f;
#pragma unroll
        for (int j = 0; j < 8; j++) {
#pragma unroll
            for (int q = 0; q < 4; q++) {
                int ch = (j * 2 + half) * 4 + q;
                as = fmaf(acc[4*j+q], as_s[ch], as);
                ad = fmaf(acc[4*j+q], ad_s[ch], ad);
            }
        }
        as += __shfl_xor_sync(0xffffffffu, as, 1);
        ad += __shfl_xor_sync(0xffffffffu, ad, 1);
        if (valid) {
            if (half == 0) { g_as[node] = as; g_ad[node] = ad; }
            float4* o4 = (float4*)&out[(size_t)node * H];
#pragma unroll
            for (int j = 0; j < 8; j++)
                o4[j * 2 + half] = make_float4(acc[4*j], acc[4*j+1], acc[4*j+2], acc[4*j+3]);
        }
    }
}

// ---------------- GEMM3 + heads fused: h3 = relu(dinv*(u@W3)+b3); opt/bottleneck/embed ----
__global__ void __launch_bounds__(256) k_gemm3_heads(
    const float* __restrict__ in, const float* __restrict__ W,
    const float* __restrict__ b3,
    const float* __restrict__ Wopt, const float* __restrict__ bopt,
    const float* __restrict__ Wb1,  const float* __restrict__ bb1,
    const float* __restrict__ Wb2,  const float* __restrict__ bb2,
    float* __restrict__ out_opt, float* __restrict__ out_bot, int n)
{
    constexpr int K = 64, PAD = K + 1;
    __shared__ float Ws[K * H];
    __shared__ float xs[128 * PAD];
    __shared__ float bs[H];
    __shared__ float sWopt[H * 10], sbopt[10], sWb1[H * 32], sbb1[32], sWb2[32], sbb2[1];
    __shared__ float sEmb[H];
    const int tid  = threadIdx.x;
    const int base = blockIdx.x * 128;

    for (int i = tid; i < K * H; i += 256) Ws[i] = W[i];
    for (int i = tid; i < H * 10; i += 256) sWopt[i] = Wopt[i];
    for (int i = tid; i < H * 32; i += 256) sWb1[i] = Wb1[i];
    if (tid < H)  { bs[tid] = b3[tid]; sEmb[tid] = 0.f; }
    if (tid < 32) { sbb1[tid] = bb1[tid]; sWb2[tid] = Wb2[tid]; }
    if (tid < 10) sbopt[tid] = bopt[tid];
    if (tid == 0) sbb2[0] = bb2[0];

    int rows = n - base; if (rows > 128) rows = 128;
    for (int i = tid; i < rows * K; i += 256) {
        int r = i / K, c = i - r * K;
        xs[r * PAD + c] = in[(size_t)(base + r) * K + c];
    }
    __syncthreads();

    const int r     = tid >> 1;
    const bool valid = (r < rows);
    const int rc    = valid ? r : 0;
    const int half  = tid & 1;

    float acc[32];
#pragma unroll
    for (int j = 0; j < 32; j++) acc[j] = 0.f;

    const float* xrow = &xs[rc * PAD];
#pragma unroll 4
    for (int k = 0; k < K; k++) {
        float xv = xrow[k];
        const float4* w4 = (const float4*)&Ws[k * H];
#pragma unroll
        for (int j = 0; j < 8; j++) {
            float4 w = w4[j * 2 + half];
            acc[4*j+0] = fmaf(xv, w.x, acc[4*j+0]);
            acc[4*j+1] = fmaf(xv, w.y, acc[4*j+1]);
            acc[4*j+2] = fmaf(xv, w.z, acc[4*j+2]);
            acc[4*j+3] = fmaf(xv, w.w, acc[4*j+3]);
        }
    }

    const int node = base + r;
    float d = valid ? g_dinv[node] : 0.f;

    // h3 in place of acc: relu(d*acc + b3[ch]); force 0 for invalid threads
#pragma unroll
    for (int j = 0; j < 8; j++) {
#pragma unroll
        for (int q = 0; q < 4; q++) {
            int ch = (j * 2 + half) * 4 + q;
            float v = fmaxf(fmaf(acc[4*j+q], d, bs[ch]), 0.f);
            acc[4*j+q] = valid ? v : 0.f;
        }
    }

    // opt logits: 10 dots, combine halves via shfl
#pragma unroll
    for (int c = 0; c < 10; c++) {
        float p = 0.f;
#pragma unroll
        for (int j = 0; j < 8; j++) {
#pragma unroll
            for (int q = 0; q < 4; q++) {
                int ch = (j * 2 + half) * 4 + q;
                p = fmaf(acc[4*j+q], sWopt[ch * 10 + c], p);
            }
        }
        p += __shfl_xor_sync(0xffffffffu, p, 1);
        if (valid && half == 0) out_opt[(size_t)node * 10 + c] = p + sbopt[c];
    }

    // bottleneck MLP
    float z = 0.f;
#pragma unroll
    for (int m = 0; m < 32; m++) {
        float s = 0.f;
#pragma unroll
        for (int j = 0; j < 8; j++) {
#pragma unroll
            for (int q = 0; q < 4; q++) {
                int ch = (j * 2 + half) * 4 + q;
                s = fmaf(acc[4*j+q], sWb1[ch * 32 + m], s);
            }
        }
        s += __shfl_xor_sync(0xffffffffu, s, 1);
        z = fmaf(fmaxf(s + sbb1[m], 0.f), sWb2[m], z);
    }
    if (valid && half == 0) out_bot[node] = 1.f / (1.f + expf(-(z + sbb2[0])));

    // embedding: parity-preserving warp reduce (lanes of same half), then smem, then global
    const int lane = tid & 31;
#pragma unroll
    for (int idx = 0; idx < 32; idx++) {
        float v = acc[idx];
        v += __shfl_xor_sync(0xffffffffu, v, 2);
        v += __shfl_xor_sync(0xffffffffu, v, 4);
        v += __shfl_xor_sync(0xffffffffu, v, 8);
        v += __shfl_xor_sync(0xffffffffu, v, 16);
        if (lane < 2) {
            int ch = ((idx >> 2) * 2 + half) * 4 + (idx & 3);
            atomicAdd(&sEmb[ch], v);
        }
    }
    __syncthreads();
    if (tid < H) atomicAdd(&g_embed[tid], sEmb[tid]);
}

// ---------------- GAT gather: softmax-max, then fused p/denom/weighted gather + epilogue ----
__global__ void __launch_bounds__(256) k_gat_gather(
    const float* __restrict__ h2, const float* __restrict__ b2,
    float* __restrict__ out, int n)
{
    int t = blockIdx.x * blockDim.x + threadIdx.x;
    int node = t >> 4;
    int c = t & 15;
    bool valid = (node < n);
    int nd = valid ? node : 0;

    int beg = g_row[nd], end = g_row[nd + 1];
    if (!valid) { beg = 0; end = 0; }

    float ad_d   = g_ad[nd];
    float eself  = leaky(g_as[nd] + ad_d);

    // pass 1: max over incoming edges (edge-parallel across the 16 lanes)
    float m = eself;
    for (int i = beg + c; i < end; i += 16) {
        int s = __ldg(&g_csrc[i]);
        m = fmaxf(m, leaky(__ldg(&g_as[s]) + ad_d));
    }
#pragma unroll
    for (int o = 8; o; o >>= 1)
        m = fmaxf(m, __shfl_xor_sync(0xffffffffu, m, o));   // stays in 16-lane group

    // pass 2: accumulate p*h2[src] and denom (channel-parallel), 2 edges in flight
    float4 acc = make_float4(0.f, 0.f, 0.f, 0.f);
    float den = 0.f;
    int i = beg;
    for (; i + 2 <= end; i += 2) {
        int s0 = __ldg(&g_csrc[i]);
        int s1 = __ldg(&g_csrc[i + 1]);
        float p0 = __expf(leaky(__ldg(&g_as[s0]) + ad_d) - m);
        float p1 = __expf(leaky(__ldg(&g_as[s1]) + ad_d) - m);
        float4 v0 = __ldg((const float4*)h2 + (size_t)s0 * 16 + c);
        float4 v1 = __ldg((const float4*)h2 + (size_t)s1 * 16 + c);
        acc.x += p0 * v0.x + p1 * v1.x;
        acc.y += p0 * v0.y + p1 * v1.y;
        acc.z += p0 * v0.z + p1 * v1.z;
        acc.w += p0 * v0.w + p1 * v1.w;
        den += p0 + p1;
    }
    if (i < end) {
        int s0 = __ldg(&g_csrc[i]);
        float p0 = __expf(leaky(__ldg(&g_as[s0]) + ad_d) - m);
        float4 v0 = __ldg((const float4*)h2 + (size_t)s0 * 16 + c);
        acc.x += p0 * v0.x; acc.y += p0 * v0.y;
        acc.z += p0 * v0.z; acc.w += p0 * v0.w;
        den += p0;
    }
    if (!valid) return;

    float pself = __expf(eself - m);
    float w = 1.f / (den + pself);
    float4 hd = __ldg((const float4*)h2 + (size_t)node * 16 + c);
    float4 bb = __ldg((const float4*)b2 + c);
    float4 rr;
    rr.x = fmaxf(fmaf(acc.x + pself * hd.x, w, bb.x), 0.f);
    rr.y = fmaxf(fmaf(acc.y + pself * hd.y, w, bb.y), 0.f);
    rr.z = fmaxf(fmaf(acc.z + pself * hd.z, w, bb.z), 0.f);
    rr.w = fmaxf(fmaf(acc.w + pself * hd.w, w, bb.w), 0.f);
    ((float4*)&out[(size_t)node * H])[c] = rr;
}

__global__ void k_embed_final(float* __restrict__ emb_out, float inv_n) {
    int t = threadIdx.x;
    if (t < H) emb_out[t] = g_embed[t] * inv_n;
}

// ---------------- launcher ----------------
extern "C" void kernel_launch(void* const* d_in, const int* in_sizes, int n_in,
                              void* d_out, int out_size)
{
    const float* x    = (const float*)d_in[0];
    const int*   ei   = (const int*)  d_in[1];
    const float* W1   = (const float*)d_in[2];
    const float* b1   = (const float*)d_in[3];
    const float* W2   = (const float*)d_in[4];
    const float* avs  = (const float*)d_in[5];
    const float* avd  = (const float*)d_in[6];
    const float* b2   = (const float*)d_in[7];
    const float* W3   = (const float*)d_in[8];
    const float* b3   = (const float*)d_in[9];
    const float* Wopt = (const float*)d_in[10];
    const float* bopt = (const float*)d_in[11];
    const float* Wb1  = (const float*)d_in[12];
    const float* bb1  = (const float*)d_in[13];
    const float* Wb2  = (const float*)d_in[14];
    const float* bb2  = (const float*)d_in[15];

    const int n = in_sizes[0] / 32;   // F = 32
    const int e = in_sizes[1] / 2;
    const int* src = ei;
    const int* dst = ei + e;

    float* out_opt = (float*)d_out;
    float* out_bot = out_opt + (size_t)n * 10;
    float* out_emb = out_bot + n;

    float *bufA = nullptr, *bufB = nullptr, *t32 = nullptr;
    cudaGetSymbolAddress((void**)&bufA, g_bufA);
    cudaGetSymbolAddress((void**)&bufB, g_bufB);
    cudaGetSymbolAddress((void**)&t32,  g_t32);

    const int B = 256;
    const int gN   = (n + B - 1) / B;
    const int gE   = (e + B - 1) / B;
    const int gN8  = (n * 8  + B - 1) / B;
    const int gN16 = (n * 16 + B - 1) / B;
    const int gG   = (n + 127) / 128;
    const int nb   = (n + 1023) / 1024;

    // CSR build (degree histogram -> scan -> cursor scatter)
    k_prep<<<gN, B>>>(n);
    k_deg<<<gE, B>>>(dst, e);
    k_scan1<<<nb, 1024>>>(n);
    k_scan2<<<1, 128>>>(nb);
    k_scan3<<<gN, B>>>(n, e);
    k_csr<<<gE, B>>>(src, dst, e);

    // GCN layer 1: aggregate in F=32 space, then transform
    k_gather32<<<gN8, B>>>(x, t32, n);
    k_gemm<32, 0><<<gG, 256>>>(t32, W1, bufB, b1, nullptr, nullptr, n);

    // GAT layer
    k_gemm<64, 1><<<gG, 256>>>(bufB, W2, bufA, nullptr, avs, avd, n);
    k_gat_gather<<<gN16, B>>>(bufA, b2, bufB, n);

    // GCN layer 3: aggregate-first, then fused transform + heads
    k_gather64<<<gN16, B>>>(bufB, bufA, n);
    k_gemm3_heads<<<gG, 256>>>(bufA, W3, b3, Wopt, bopt, Wb1, bb1, Wb2, bb2,
                               out_opt, out_bot, n);

    k_embed_final<<<1, 64>>>(out_emb, 1.0f / (float)n);
}